// round 13
// baseline (speedup 1.0000x reference)
#include <cuda_runtime.h>

#define NP 400000
#define SXYZ 11264000
#define SYZ 16000
#define SZ 20
#define NWORDS 704000
#define SCAN_BLOCKS 688
#define NTILES 3125

#define OFF0 (0.05f)
#define OFF1 (0.05f - 40.0f)
#define OFF2 (0.1f - 3.0f)

__device__ unsigned g_bits[NWORDS];
__device__ unsigned g_wpre[NWORDS];
__device__ unsigned g_bsum[SCAN_BLOCKS];
__device__ unsigned g_boff[SCAN_BLOCKS];
__device__ int      g_nuniq;
__device__ int      g_nmulti;
__device__ int      g_mlist[NP];
__device__ int      g_keys[NP];
__device__ int      g_inv[NP];
__device__ int      g_cnt[NP];
__device__ float    g_sums[NP * 3];
__device__ unsigned g_xmaxu[(size_t)NP * 64];   /* only multi segs used */
__device__ float    g_corr[(size_t)NP * 128];   /* only multi rows used */
__device__ float    g_wsum[8192];               /* W1a + W1b */
__device__ double   g_mom[65];                  /* Sf[10], Sff[55] */
__device__ double   g_gram[4096];               /* A = sum h0 h0^T */
__device__ double   g_s0sum[64];                /* S0 = sum h0 */
__device__ double   g_dsum[128], g_dsq[128];    /* multi-row stat deltas */
__device__ float    g_s0[64], g_t0[64], g_s1[128], g_t1[128];

__device__ __forceinline__ void coords_of(float x, float y, float z,
                                          int& cx, int& cy, int& cz) {
    cx = (int)floorf(__fmul_rn(x, 10.0f));
    cy = (int)floorf(__fmul_rn(__fadd_rn(y, 40.0f), 10.0f));
    cz = (int)floorf(__fmul_rn(__fadd_rn(z, 3.0f), 5.0f));
}
__device__ __forceinline__ unsigned utrans(float x) {
    unsigned u = __float_as_uint(x);
    return (u & 0x80000000u) ? ~u : (u | 0x80000000u);
}
__device__ __forceinline__ float uinv(unsigned u) {
    return __uint_as_float((u & 0x80000000u) ? (u & 0x7fffffffu) : ~u);
}
__device__ __forceinline__ unsigned long long pk2(float a, float b) {
    unsigned long long r;
    asm("mov.b64 %0,{%1,%2};" : "=l"(r) : "f"(a), "f"(b));
    return r;
}
__device__ __forceinline__ void upk(unsigned long long v, float& a, float& b) {
    asm("mov.b64 {%0,%1},%2;" : "=f"(a), "=f"(b) : "l"(v));
}
__device__ __forceinline__ unsigned long long fma2(unsigned long long a,
                                                   unsigned long long b,
                                                   unsigned long long c) {
    unsigned long long d;
    asm("fma.rn.f32x2 %0,%1,%2,%3;" : "=l"(d) : "l"(a), "l"(b), "l"(c));
    return d;
}

__device__ __forceinline__ void compute_feat(const float* __restrict__ pts,
                                             int i, float* f,
                                             int& seg, int& cnt) {
    float x = pts[i * 5 + 1], y = pts[i * 5 + 2], z = pts[i * 5 + 3];
    float inten = pts[i * 5 + 4];
    int cx, cy, cz;
    coords_of(x, y, z, cx, cy, cz);
    seg = g_inv[i];
    cnt = g_cnt[seg];
    float fc = fmaxf((float)cnt, 1.f);
    f[0] = x; f[1] = y; f[2] = z; f[3] = inten;
    f[4] = __fsub_rn(x, __fdiv_rn(g_sums[seg * 3 + 0], fc));
    f[5] = __fsub_rn(y, __fdiv_rn(g_sums[seg * 3 + 1], fc));
    f[6] = __fsub_rn(z, __fdiv_rn(g_sums[seg * 3 + 2], fc));
    f[7] = __fsub_rn(x, __fadd_rn(__fmul_rn((float)cx, 0.1f), OFF0));
    f[8] = __fsub_rn(y, __fadd_rn(__fmul_rn((float)cy, 0.1f), OFF1));
    f[9] = __fsub_rn(z, __fadd_rn(__fmul_rn((float)cz, 0.2f), OFF2));
}

__global__ void k_keys(const float* __restrict__ pts) {
    int i = blockIdx.x * 256 + threadIdx.x;
    if (i >= NP) return;
    float b = pts[i * 5 + 0];
    float x = pts[i * 5 + 1], y = pts[i * 5 + 2], z = pts[i * 5 + 3];
    int cx, cy, cz;
    coords_of(x, y, z, cx, cy, cz);
    int key = (int)b * SXYZ + cx * SYZ + cy * SZ + cz;
    g_keys[i] = key;
    atomicOr(&g_bits[(unsigned)key >> 5], 1u << (key & 31));
}

__global__ void k_scan_words() {
    __shared__ unsigned sh[256];
    unsigned b = blockIdx.x, t = threadIdx.x;
    unsigned base = b * 1024u + t * 4u;
    uint4 w = make_uint4(0u, 0u, 0u, 0u);
    if (base < NWORDS) w = *(const uint4*)&g_bits[base];
    unsigned c0 = __popc(w.x), c1 = __popc(w.y), c2 = __popc(w.z), c3 = __popc(w.w);
    unsigned tot = c0 + c1 + c2 + c3;
    sh[t] = tot;
    __syncthreads();
    for (int off = 1; off < 256; off <<= 1) {
        unsigned v = (t >= (unsigned)off) ? sh[t - off] : 0u;
        __syncthreads();
        sh[t] += v;
        __syncthreads();
    }
    unsigned excl = sh[t] - tot;
    if (base < NWORDS) {
        g_wpre[base + 0] = excl;
        g_wpre[base + 1] = excl + c0;
        g_wpre[base + 2] = excl + c0 + c1;
        g_wpre[base + 3] = excl + c0 + c1 + c2;
    }
    if (t == 255) g_bsum[b] = sh[255];
}

__global__ void k_scan_blocks() {
    __shared__ unsigned sh[1024];
    int t = threadIdx.x;
    unsigned v = (t < SCAN_BLOCKS) ? g_bsum[t] : 0u;
    sh[t] = v;
    __syncthreads();
    for (int off = 1; off < 1024; off <<= 1) {
        unsigned u = (t >= off) ? sh[t - off] : 0u;
        __syncthreads();
        sh[t] += u;
        __syncthreads();
    }
    if (t < SCAN_BLOCKS) g_boff[t] = sh[t] - v;
    if (t == 1023) g_nuniq = (int)sh[1023];
}

__global__ void k_inv(const float* __restrict__ pts) {
    int i = blockIdx.x * 256 + threadIdx.x;
    if (i >= NP) return;
    int key = g_keys[i];
    unsigned w = (unsigned)key >> 5, bit = key & 31;
    unsigned rank = g_boff[w >> 10] + g_wpre[w] +
                    __popc(g_bits[w] & ((1u << bit) - 1u));
    g_inv[i] = (int)rank;
    atomicAdd(&g_cnt[rank], 1);
    atomicAdd(&g_sums[rank * 3 + 0], pts[i * 5 + 1]);
    atomicAdd(&g_sums[rank * 3 + 1], pts[i * 5 + 2]);
    atomicAdd(&g_sums[rank * 3 + 2], pts[i * 5 + 3]);
}

__global__ void k_zero(float* __restrict__ out) {
    int i = blockIdx.x * 256 + threadIdx.x;
    if (i >= NP) return;
    int nu = g_nuniq;
    bool multi = (i < nu) && (g_cnt[i] > 1);
    if (i >= nu || multi) {
        float4* o = (float4*)&out[(size_t)i * 128];
        #pragma unroll
        for (int q = 0; q < 32; q++) o[q] = make_float4(0.f, 0.f, 0.f, 0.f);
    }
    if (multi) {
        uint4* xm = (uint4*)&g_xmaxu[(size_t)i * 64];
        #pragma unroll
        for (int q = 0; q < 16; q++) xm[q] = make_uint4(0u, 0u, 0u, 0u);
    }
}

__global__ void k_fillcoords(float* __restrict__ oc) {
    int i = blockIdx.x * 256 + threadIdx.x;
    if (i >= NP || i < g_nuniq) return;
    ((float4*)oc)[i] = make_float4(-1.f, 19.f, 799.f, 703.f);
}

__global__ void k_coords(float* __restrict__ oc) {
    int w = blockIdx.x * 256 + threadIdx.x;
    if (w >= NWORDS) return;
    unsigned m = g_bits[w];
    if (!m) return;
    unsigned r = g_boff[w >> 10] + g_wpre[w];
    int kb = w << 5;
    while (m) {
        int b = __ffs(m) - 1;
        m &= m - 1;
        int key = kb + b;
        int B = key / SXYZ;
        int rem = key % SXYZ;
        int X = rem / SYZ; rem -= X * SYZ;
        int Y = rem / SZ;
        int Z = rem - Y * SZ;
        ((float4*)oc)[r] = make_float4((float)B, (float)Z, (float)Y, (float)X);
        r++;
    }
}

__global__ void k_wsum(const float* __restrict__ W1) {
    int j = blockIdx.x * 256 + threadIdx.x;
    if (j < 8192) g_wsum[j] = W1[j] + W1[j + 8192];
}

/* feature moments + multi-seg xmax */
__global__ void __launch_bounds__(256) k_prep(const float* __restrict__ pts,
                                              const float* __restrict__ W0) {
    __shared__ float w0s[640];
    __shared__ float sm[65];
    int tid = threadIdx.x;
    for (int j = tid; j < 640; j += 256) w0s[j] = W0[j];
    if (tid < 65) sm[tid] = 0.f;
    __syncthreads();
    float mom[65];
    #pragma unroll
    for (int v = 0; v < 65; v++) mom[v] = 0.f;
    int base = blockIdx.x * 2048;
    for (int i = base + tid; i < base + 2048 && i < NP; i += 256) {
        float f[10];
        int seg, cnt;
        compute_feat(pts, i, f, seg, cnt);
        #pragma unroll
        for (int k = 0; k < 10; k++) mom[k] += f[k];
        {
            int idx = 10;
            #pragma unroll
            for (int k = 0; k < 10; k++)
                #pragma unroll
                for (int l = k; l < 10; l++)
                    mom[idx++] += f[k] * f[l];
        }
        if (cnt > 1) {
            int mi = atomicAdd(&g_nmulti, 1);
            g_mlist[mi] = i;
            unsigned* xm = &g_xmaxu[(size_t)seg * 64];
            #pragma unroll 8
            for (int c = 0; c < 64; c++) {
                float acc = 0.f;
                #pragma unroll
                for (int k = 0; k < 10; k++) acc = fmaf(f[k], w0s[k * 64 + c], acc);
                atomicMax(&xm[c], utrans(acc));
            }
        }
    }
    int lane = tid & 31;
    #pragma unroll
    for (int v = 0; v < 65; v++) {
        float s = mom[v];
        #pragma unroll
        for (int o = 16; o; o >>= 1) s += __shfl_down_sync(0xffffffffu, s, o);
        if (lane == 0) atomicAdd(&sm[v], s);
    }
    __syncthreads();
    if (tid < 65) atomicAdd(&g_mom[tid], (double)sm[tid]);
}

__global__ void k_bn0(const float* __restrict__ W0,
                      const float* __restrict__ g, const float* __restrict__ b) {
    int c = threadIdx.x;
    if (c >= 64) return;
    double w[10];
    #pragma unroll
    for (int k = 0; k < 10; k++) w[k] = (double)W0[k * 64 + c];
    double mean = 0.0;
    #pragma unroll
    for (int k = 0; k < 10; k++) mean += w[k] * g_mom[k];
    mean /= (double)NP;
    double ey2 = 0.0;
    int idx = 10;
    #pragma unroll
    for (int k = 0; k < 10; k++)
        #pragma unroll
        for (int l = k; l < 10; l++) {
            double t = w[k] * w[l] * g_mom[idx++];
            ey2 += (k == l) ? t : 2.0 * t;
        }
    ey2 /= (double)NP;
    double var = ey2 - mean * mean;
    double s = (double)g[c] / sqrt(var + 0.001);
    g_s0[c] = (float)s;
    g_t0[c] = (float)((double)b[c] - mean * s);
}

/* Gram A = sum h0 h0^T and S0 = sum h0 — register-tiled XtX.
   256 thr = 4 q-slices x (8 row-groups x 8 col-groups), 8x8 patch/thread.
   S0 accumulated in registers across tiles; one combine at kernel end. */
__global__ void __launch_bounds__(256) k_gram(const float* __restrict__ pts,
                                              const float* __restrict__ W0) {
    __shared__ float xs[128 * 66];    /* point-major, pad 66 (8B-aligned rows) */
    __shared__ float w0s[640];
    __shared__ float sS[64], sT[64];
    __shared__ float s0s[64];
    __shared__ float gred[4096];
    int tid = threadIdx.x;
    for (int j = tid; j < 640; j += 256) w0s[j] = W0[j];
    for (int j = tid; j < 4096; j += 256) gred[j] = 0.f;
    if (tid < 64) { sS[tid] = g_s0[tid]; sT[tid] = g_t0[tid]; s0s[tid] = 0.f; }
    __syncthreads();

    int qs = tid >> 6;             /* q-slice: q in [qs*32, qs*32+32) */
    int rg = (tid >> 3) & 7;       /* rows rg*8 .. +7 */
    int cg = tid & 7;              /* cols cg*8 .. +7 */
    int m = tid & 127, half = tid >> 7;

    unsigned long long acc[8][4];
    #pragma unroll
    for (int i = 0; i < 8; i++)
        #pragma unroll
        for (int j = 0; j < 4; j++) acc[i][j] = 0ull;
    float sacc[32];
    #pragma unroll
    for (int c = 0; c < 32; c++) sacc[c] = 0.f;

    for (int t = blockIdx.x; t < NTILES; t += gridDim.x) {
        int pt = t * 128 + m;      /* NP == NTILES*128 exactly */
        float f[10];
        int seg, cnt;
        compute_feat(pts, pt, f, seg, cnt);
        int cb = half * 32;
        #pragma unroll 8
        for (int cc = 0; cc < 32; cc++) {
            int c = cb + cc;
            float a = 0.f;
            #pragma unroll
            for (int k = 0; k < 10; k++) a = fmaf(f[k], w0s[k * 64 + c], a);
            float h = fmaxf(fmaf(a, sS[c], sT[c]), 0.f);
            xs[m * 66 + c] = h;
            sacc[cc] += h;
        }
        __syncthreads();
        #pragma unroll 2
        for (int q = qs * 32; q < qs * 32 + 32; q++) {
            const float* row = &xs[q * 66];
            unsigned long long av0 = *(const unsigned long long*)&row[rg * 8 + 0];
            unsigned long long av1 = *(const unsigned long long*)&row[rg * 8 + 2];
            unsigned long long av2 = *(const unsigned long long*)&row[rg * 8 + 4];
            unsigned long long av3 = *(const unsigned long long*)&row[rg * 8 + 6];
            unsigned long long b0 = *(const unsigned long long*)&row[cg * 8 + 0];
            unsigned long long b1 = *(const unsigned long long*)&row[cg * 8 + 2];
            unsigned long long b2 = *(const unsigned long long*)&row[cg * 8 + 4];
            unsigned long long b3 = *(const unsigned long long*)&row[cg * 8 + 6];
            float a0, a1, a2, a3, a4, a5, a6, a7;
            upk(av0, a0, a1); upk(av1, a2, a3);
            upk(av2, a4, a5); upk(av3, a6, a7);
            unsigned long long am;
            am = pk2(a0, a0);
            acc[0][0] = fma2(am, b0, acc[0][0]); acc[0][1] = fma2(am, b1, acc[0][1]);
            acc[0][2] = fma2(am, b2, acc[0][2]); acc[0][3] = fma2(am, b3, acc[0][3]);
            am = pk2(a1, a1);
            acc[1][0] = fma2(am, b0, acc[1][0]); acc[1][1] = fma2(am, b1, acc[1][1]);
            acc[1][2] = fma2(am, b2, acc[1][2]); acc[1][3] = fma2(am, b3, acc[1][3]);
            am = pk2(a2, a2);
            acc[2][0] = fma2(am, b0, acc[2][0]); acc[2][1] = fma2(am, b1, acc[2][1]);
            acc[2][2] = fma2(am, b2, acc[2][2]); acc[2][3] = fma2(am, b3, acc[2][3]);
            am = pk2(a3, a3);
            acc[3][0] = fma2(am, b0, acc[3][0]); acc[3][1] = fma2(am, b1, acc[3][1]);
            acc[3][2] = fma2(am, b2, acc[3][2]); acc[3][3] = fma2(am, b3, acc[3][3]);
            am = pk2(a4, a4);
            acc[4][0] = fma2(am, b0, acc[4][0]); acc[4][1] = fma2(am, b1, acc[4][1]);
            acc[4][2] = fma2(am, b2, acc[4][2]); acc[4][3] = fma2(am, b3, acc[4][3]);
            am = pk2(a5, a5);
            acc[5][0] = fma2(am, b0, acc[5][0]); acc[5][1] = fma2(am, b1, acc[5][1]);
            acc[5][2] = fma2(am, b2, acc[5][2]); acc[5][3] = fma2(am, b3, acc[5][3]);
            am = pk2(a6, a6);
            acc[6][0] = fma2(am, b0, acc[6][0]); acc[6][1] = fma2(am, b1, acc[6][1]);
            acc[6][2] = fma2(am, b2, acc[6][2]); acc[6][3] = fma2(am, b3, acc[6][3]);
            am = pk2(a7, a7);
            acc[7][0] = fma2(am, b0, acc[7][0]); acc[7][1] = fma2(am, b1, acc[7][1]);
            acc[7][2] = fma2(am, b2, acc[7][2]); acc[7][3] = fma2(am, b3, acc[7][3]);
        }
        __syncthreads();
    }
    /* combine slices: float smem atomics (spread addresses) */
    #pragma unroll
    for (int i = 0; i < 8; i++)
        #pragma unroll
        for (int j = 0; j < 4; j++) {
            float v0, v1;
            upk(acc[i][j], v0, v1);
            int idx = (rg * 8 + i) * 64 + cg * 8 + 2 * j;
            atomicAdd(&gred[idx],     v0);
            atomicAdd(&gred[idx + 1], v1);
        }
    /* S0 registers -> smem */
    #pragma unroll
    for (int cc = 0; cc < 32; cc++)
        atomicAdd(&s0s[half * 32 + cc], sacc[cc]);
    __syncthreads();
    for (int j = tid; j < 4096; j += 256)
        atomicAdd(&g_gram[j], (double)gred[j]);
    if (tid < 64) atomicAdd(&g_s0sum[tid], (double)s0s[tid]);
}

/* multi-row correction: corr = d @ W1b, plus exact stat deltas */
__global__ void k_corr(const float* __restrict__ pts,
                       const float* __restrict__ W0,
                       const float* __restrict__ W1) {
    __shared__ float w0s[640];
    __shared__ float hv[64], dv[64];
    int tid = threadIdx.x;   /* 128 */
    for (int j = tid; j < 640; j += 128) w0s[j] = W0[j];
    __syncthreads();
    double dsum = 0.0, dsq = 0.0;
    int nm = g_nmulti;
    for (int it = blockIdx.x; it < nm; it += gridDim.x) {
        int p = g_mlist[it];
        float f[10];
        int seg, cnt;
        compute_feat(pts, p, f, seg, cnt);
        if (tid < 64) {
            float acc = 0.f;
            #pragma unroll
            for (int k = 0; k < 10; k++) acc = fmaf(f[k], w0s[k * 64 + tid], acc);
            float h0 = fmaxf(fmaf(acc, g_s0[tid], g_t0[tid]), 0.f);
            float hm = fmaxf(fmaf(uinv(g_xmaxu[(size_t)seg * 64 + tid]),
                                  g_s0[tid], g_t0[tid]), 0.f);
            hv[tid] = h0;
            dv[tid] = hm - h0;
        }
        __syncthreads();
        float ya = 0.f, co = 0.f;
        #pragma unroll 8
        for (int k = 0; k < 64; k++) ya = fmaf(hv[k], g_wsum[k * 128 + tid], ya);
        #pragma unroll 8
        for (int k = 0; k < 64; k++) co = fmaf(dv[k], W1[(64 + k) * 128 + tid], co);
        g_corr[(size_t)p * 128 + tid] = co;
        float nw = ya + co;
        dsum += (double)co;
        dsq  += (double)nw * (double)nw - (double)ya * (double)ya;
        __syncthreads();
    }
    atomicAdd(&g_dsum[tid], dsum);
    atomicAdd(&g_dsq[tid], dsq);
}

/* BN1 stats from Gram: one block per output column */
__global__ void k_bn1(const float* __restrict__ g, const float* __restrict__ b) {
    int c = blockIdx.x;
    int k = threadIdx.x;   /* 64 */
    __shared__ double wsd[64];
    __shared__ double red[64], red2[64];
    wsd[k] = (double)g_wsum[k * 128 + c];
    __syncthreads();
    double p = 0.0;
    #pragma unroll 8
    for (int l = 0; l < 64; l++) p += g_gram[k * 64 + l] * wsd[l];
    red[k]  = p * wsd[k];
    red2[k] = g_s0sum[k] * wsd[k];
    __syncthreads();
    for (int o = 32; o; o >>= 1) {
        if (k < o) { red[k] += red[k + o]; red2[k] += red2[k + o]; }
        __syncthreads();
    }
    if (k == 0) {
        double sum = red2[0] + g_dsum[c];
        double sq  = red[0]  + g_dsq[c];
        double m = sum / (double)NP;
        double var = sq / (double)NP - m * m;
        double s = (double)g[c] / sqrt(var + 0.001);
        g_s1[c] = (float)s;
        g_t1[c] = (float)((double)b[c] - m * s);
    }
}

/* fused GEMM + BN1 + relu + segment-max, writes out directly */
__global__ void __launch_bounds__(256, 2) k_gemm_out(const float* __restrict__ pts,
                                                     const float* __restrict__ W0,
                                                     float* __restrict__ out) {
    extern __shared__ float sh[];
    float* ws = sh;            /* 64*128 */
    float* xs = sh + 8192;     /* 64*132 */
    __shared__ float w0s[640];
    __shared__ float sS[64], sT[64];
    __shared__ float ss1[128], st1[128];
    int tid = threadIdx.x;
    if (tid < 64)  { sS[tid] = g_s0[tid]; sT[tid] = g_t0[tid]; }
    if (tid < 128) { ss1[tid] = g_s1[tid]; st1[tid] = g_t1[tid]; }
    for (int j = tid; j < 640; j += 256) w0s[j] = W0[j];
    {
        const float4* w4 = (const float4*)g_wsum;
        float4* ws4 = (float4*)ws;
        for (int j = tid; j < 2048; j += 256) ws4[j] = w4[j];
    }
    __syncthreads();

    int bs = blockIdx.x * 128;
    {
        int m = tid & 127, half = tid >> 7;
        float f[10];
        int seg, cnt;
        compute_feat(pts, bs + m, f, seg, cnt);
        int cbase = half * 32;
        #pragma unroll 8
        for (int c = cbase; c < cbase + 32; c++) {
            float acc = 0.f;
            #pragma unroll
            for (int k = 0; k < 10; k++) acc = fmaf(f[k], w0s[k * 64 + c], acc);
            xs[c * 132 + m] = fmaxf(fmaf(acc, sS[c], sT[c]), 0.f);
        }
    }
    __syncthreads();

    int tx = tid & 15, ty = tid >> 4;
    unsigned long long acc[8][4];
    #pragma unroll
    for (int i = 0; i < 8; i++)
        #pragma unroll
        for (int p = 0; p < 4; p++) acc[i][p] = 0ull;

    #pragma unroll 2
    for (int k = 0; k < 64; k++) {
        float4 a0 = *(const float4*)&xs[k * 132 + ty * 8];
        float4 a1 = *(const float4*)&xs[k * 132 + ty * 8 + 4];
        unsigned long long am[8];
        am[0] = pk2(a0.x, a0.x); am[1] = pk2(a0.y, a0.y);
        am[2] = pk2(a0.z, a0.z); am[3] = pk2(a0.w, a0.w);
        am[4] = pk2(a1.x, a1.x); am[5] = pk2(a1.y, a1.y);
        am[6] = pk2(a1.z, a1.z); am[7] = pk2(a1.w, a1.w);
        ulonglong2 b0 = *(const ulonglong2*)&ws[k * 128 + tx * 8];
        ulonglong2 b1 = *(const ulonglong2*)&ws[k * 128 + tx * 8 + 4];
        #pragma unroll
        for (int i = 0; i < 8; i++) {
            acc[i][0] = fma2(am[i], b0.x, acc[i][0]);
            acc[i][1] = fma2(am[i], b0.y, acc[i][1]);
            acc[i][2] = fma2(am[i], b1.x, acc[i][2]);
            acc[i][3] = fma2(am[i], b1.y, acc[i][3]);
        }
    }

    #pragma unroll
    for (int i = 0; i < 8; i++) {
        float v[8];
        #pragma unroll
        for (int p = 0; p < 4; p++) upk(acc[i][p], v[2 * p], v[2 * p + 1]);
        int pt = bs + ty * 8 + i;
        int seg = g_inv[pt];
        int cnt = g_cnt[seg];
        if (cnt > 1) {
            const float4* cr = (const float4*)&g_corr[(size_t)pt * 128 + tx * 8];
            float4 c0 = cr[0], c1 = cr[1];
            v[0] += c0.x; v[1] += c0.y; v[2] += c0.z; v[3] += c0.w;
            v[4] += c1.x; v[5] += c1.y; v[6] += c1.z; v[7] += c1.w;
        }
        float h[8];
        #pragma unroll
        for (int j = 0; j < 8; j++)
            h[j] = fmaxf(fmaf(v[j], ss1[tx * 8 + j], st1[tx * 8 + j]), 0.f);
        if (cnt == 1) {
            float4* dst = (float4*)&out[(size_t)seg * 128 + tx * 8];
            dst[0] = make_float4(h[0], h[1], h[2], h[3]);
            dst[1] = make_float4(h[4], h[5], h[6], h[7]);
        } else {
            int* ob = (int*)&out[(size_t)seg * 128 + tx * 8];
            #pragma unroll
            for (int j = 0; j < 8; j++)
                atomicMax(&ob[j], __float_as_int(h[j]));
        }
    }
}

extern "C" void kernel_launch(void* const* d_in, const int* in_sizes, int n_in,
                              void* d_out, int out_size) {
    const float* pts = (const float*)d_in[0];
    const float* W0  = (const float*)d_in[1];
    const float* g0  = (const float*)d_in[2];
    const float* b0  = (const float*)d_in[3];
    const float* W1  = (const float*)d_in[4];
    const float* g1  = (const float*)d_in[5];
    const float* b1  = (const float*)d_in[6];
    float* out = (float*)d_out;
    float* oc = out + (size_t)NP * 128;
    int emit_coords = ((long long)out_size >= (long long)NP * 132);

    void *p_bits, *p_cnt, *p_sums, *p_nm, *p_mom, *p_gram, *p_s0s, *p_ds, *p_dq;
    cudaGetSymbolAddress(&p_bits, g_bits);
    cudaGetSymbolAddress(&p_cnt,  g_cnt);
    cudaGetSymbolAddress(&p_sums, g_sums);
    cudaGetSymbolAddress(&p_nm,   g_nmulti);
    cudaGetSymbolAddress(&p_mom,  g_mom);
    cudaGetSymbolAddress(&p_gram, g_gram);
    cudaGetSymbolAddress(&p_s0s,  g_s0sum);
    cudaGetSymbolAddress(&p_ds,   g_dsum);
    cudaGetSymbolAddress(&p_dq,   g_dsq);

    cudaMemsetAsync(p_bits, 0, NWORDS * 4);
    cudaMemsetAsync(p_cnt,  0, NP * 4);
    cudaMemsetAsync(p_sums, 0, NP * 12);
    cudaMemsetAsync(p_nm,   0, 4);
    cudaMemsetAsync(p_mom,  0, 65 * 8);
    cudaMemsetAsync(p_gram, 0, 4096 * 8);
    cudaMemsetAsync(p_s0s,  0, 64 * 8);
    cudaMemsetAsync(p_ds,   0, 128 * 8);
    cudaMemsetAsync(p_dq,   0, 128 * 8);

    k_keys<<<1563, 256>>>(pts);
    k_scan_words<<<SCAN_BLOCKS, 256>>>();
    k_scan_blocks<<<1, 1024>>>();
    k_inv<<<1563, 256>>>(pts);
    k_zero<<<1563, 256>>>(out);
    if (emit_coords) {
        k_fillcoords<<<1563, 256>>>(oc);
        k_coords<<<2750, 256>>>(oc);
    }
    k_wsum<<<32, 256>>>(W1);
    k_prep<<<196, 256>>>(pts, W0);
    k_bn0<<<1, 64>>>(W0, g0, b0);
    k_gram<<<148, 256>>>(pts, W0);
    k_corr<<<592, 128>>>(pts, W0, W1);
    k_bn1<<<128, 64>>>(g1, b1);
    cudaFuncSetAttribute(k_gemm_out, cudaFuncAttributeMaxDynamicSharedMemorySize, 66560);
    k_gemm_out<<<3125, 256, 66560>>>(pts, W0, out);
}

// round 14
// speedup vs baseline: 1.3712x; 1.3712x over previous
#include <cuda_runtime.h>

#define NP 400000
#define SXYZ 11264000
#define SYZ 16000
#define SZ 20
#define NWORDS 704000
#define SCAN_BLOCKS 688

#define OFF0 (0.05f)
#define OFF1 (0.05f - 40.0f)
#define OFF2 (0.1f - 3.0f)

__device__ unsigned g_bits[NWORDS];
__device__ unsigned g_wpre[NWORDS];
__device__ unsigned g_bsum[SCAN_BLOCKS];
__device__ unsigned g_boff[SCAN_BLOCKS];
__device__ int      g_nuniq;
__device__ int      g_nmulti;
__device__ int      g_mlist[NP];
__device__ int      g_keys[NP];
__device__ int      g_inv[NP];
__device__ int      g_cnt[NP];
__device__ float    g_sums[NP * 3];
__device__ unsigned g_xmaxu[(size_t)NP * 64];   /* only multi segs used */
__device__ float    g_y1[(size_t)NP * 128];
__device__ float    g_wsum[8192];               /* W1a + W1b */
__device__ double   g_mom[65];                  /* Sf[10], Sff[55] */
__device__ double   g_st[384];                  /* [128:256) sum1, [256:384) sumsq1 */
__device__ float    g_s0[64], g_t0[64], g_s1[128], g_t1[128];

__device__ __forceinline__ void coords_of(float x, float y, float z,
                                          int& cx, int& cy, int& cz) {
    cx = (int)floorf(__fmul_rn(x, 10.0f));
    cy = (int)floorf(__fmul_rn(__fadd_rn(y, 40.0f), 10.0f));
    cz = (int)floorf(__fmul_rn(__fadd_rn(z, 3.0f), 5.0f));
}
__device__ __forceinline__ unsigned utrans(float x) {
    unsigned u = __float_as_uint(x);
    return (u & 0x80000000u) ? ~u : (u | 0x80000000u);
}
__device__ __forceinline__ float uinv(unsigned u) {
    return __uint_as_float((u & 0x80000000u) ? (u & 0x7fffffffu) : ~u);
}
__device__ __forceinline__ unsigned long long pk2(float a, float b) {
    unsigned long long r;
    asm("mov.b64 %0,{%1,%2};" : "=l"(r) : "f"(a), "f"(b));
    return r;
}
__device__ __forceinline__ void upk(unsigned long long v, float& a, float& b) {
    asm("mov.b64 {%0,%1},%2;" : "=f"(a), "=f"(b) : "l"(v));
}
__device__ __forceinline__ unsigned long long fma2(unsigned long long a,
                                                   unsigned long long b,
                                                   unsigned long long c) {
    unsigned long long d;
    asm("fma.rn.f32x2 %0,%1,%2,%3;" : "=l"(d) : "l"(a), "l"(b), "l"(c));
    return d;
}

__device__ __forceinline__ void compute_feat(const float* __restrict__ pts,
                                             int i, float* f,
                                             int& seg, int& cnt) {
    float x = pts[i * 5 + 1], y = pts[i * 5 + 2], z = pts[i * 5 + 3];
    float inten = pts[i * 5 + 4];
    int cx, cy, cz;
    coords_of(x, y, z, cx, cy, cz);
    seg = g_inv[i];
    cnt = g_cnt[seg];
    float fc = fmaxf((float)cnt, 1.f);
    f[0] = x; f[1] = y; f[2] = z; f[3] = inten;
    f[4] = __fsub_rn(x, __fdiv_rn(g_sums[seg * 3 + 0], fc));
    f[5] = __fsub_rn(y, __fdiv_rn(g_sums[seg * 3 + 1], fc));
    f[6] = __fsub_rn(z, __fdiv_rn(g_sums[seg * 3 + 2], fc));
    f[7] = __fsub_rn(x, __fadd_rn(__fmul_rn((float)cx, 0.1f), OFF0));
    f[8] = __fsub_rn(y, __fadd_rn(__fmul_rn((float)cy, 0.1f), OFF1));
    f[9] = __fsub_rn(z, __fadd_rn(__fmul_rn((float)cz, 0.2f), OFF2));
}

__global__ void k_keys(const float* __restrict__ pts) {
    int i = blockIdx.x * 256 + threadIdx.x;
    if (i >= NP) return;
    float b = pts[i * 5 + 0];
    float x = pts[i * 5 + 1], y = pts[i * 5 + 2], z = pts[i * 5 + 3];
    int cx, cy, cz;
    coords_of(x, y, z, cx, cy, cz);
    int key = (int)b * SXYZ + cx * SYZ + cy * SZ + cz;
    g_keys[i] = key;
    atomicOr(&g_bits[(unsigned)key >> 5], 1u << (key & 31));
}

__global__ void k_scan_words() {
    __shared__ unsigned sh[256];
    unsigned b = blockIdx.x, t = threadIdx.x;
    unsigned base = b * 1024u + t * 4u;
    uint4 w = make_uint4(0u, 0u, 0u, 0u);
    if (base < NWORDS) w = *(const uint4*)&g_bits[base];
    unsigned c0 = __popc(w.x), c1 = __popc(w.y), c2 = __popc(w.z), c3 = __popc(w.w);
    unsigned tot = c0 + c1 + c2 + c3;
    sh[t] = tot;
    __syncthreads();
    for (int off = 1; off < 256; off <<= 1) {
        unsigned v = (t >= (unsigned)off) ? sh[t - off] : 0u;
        __syncthreads();
        sh[t] += v;
        __syncthreads();
    }
    unsigned excl = sh[t] - tot;
    if (base < NWORDS) {
        g_wpre[base + 0] = excl;
        g_wpre[base + 1] = excl + c0;
        g_wpre[base + 2] = excl + c0 + c1;
        g_wpre[base + 3] = excl + c0 + c1 + c2;
    }
    if (t == 255) g_bsum[b] = sh[255];
}

__global__ void k_scan_blocks() {
    __shared__ unsigned sh[1024];
    int t = threadIdx.x;
    unsigned v = (t < SCAN_BLOCKS) ? g_bsum[t] : 0u;
    sh[t] = v;
    __syncthreads();
    for (int off = 1; off < 1024; off <<= 1) {
        unsigned u = (t >= off) ? sh[t - off] : 0u;
        __syncthreads();
        sh[t] += u;
        __syncthreads();
    }
    if (t < SCAN_BLOCKS) g_boff[t] = sh[t] - v;
    if (t == 1023) g_nuniq = (int)sh[1023];
}

__global__ void k_inv(const float* __restrict__ pts) {
    int i = blockIdx.x * 256 + threadIdx.x;
    if (i >= NP) return;
    int key = g_keys[i];
    unsigned w = (unsigned)key >> 5, bit = key & 31;
    unsigned rank = g_boff[w >> 10] + g_wpre[w] +
                    __popc(g_bits[w] & ((1u << bit) - 1u));
    g_inv[i] = (int)rank;
    atomicAdd(&g_cnt[rank], 1);
    atomicAdd(&g_sums[rank * 3 + 0], pts[i * 5 + 1]);
    atomicAdd(&g_sums[rank * 3 + 1], pts[i * 5 + 2]);
    atomicAdd(&g_sums[rank * 3 + 2], pts[i * 5 + 3]);
}

/* zero out rows not fully overwritten + fill pad coords (merged) */
__global__ void k_zero(float* __restrict__ out, float* __restrict__ oc,
                       int emit_coords) {
    int i = blockIdx.x * 256 + threadIdx.x;
    if (i >= NP) return;
    int nu = g_nuniq;
    bool tail = i >= nu;
    bool multi = !tail && (g_cnt[i] > 1);
    if (tail || multi) {
        float4* o = (float4*)&out[(size_t)i * 128];
        #pragma unroll
        for (int q = 0; q < 32; q++) o[q] = make_float4(0.f, 0.f, 0.f, 0.f);
    }
    if (multi) {
        uint4* xm = (uint4*)&g_xmaxu[(size_t)i * 64];
        #pragma unroll
        for (int q = 0; q < 16; q++) xm[q] = make_uint4(0u, 0u, 0u, 0u);
    }
    if (tail && emit_coords)
        ((float4*)oc)[i] = make_float4(-1.f, 19.f, 799.f, 703.f);
}

__global__ void k_coords(float* __restrict__ oc) {
    int w = blockIdx.x * 256 + threadIdx.x;
    if (w >= NWORDS) return;
    unsigned m = g_bits[w];
    if (!m) return;
    unsigned r = g_boff[w >> 10] + g_wpre[w];
    int kb = w << 5;
    while (m) {
        int b = __ffs(m) - 1;
        m &= m - 1;
        int key = kb + b;
        int B = key / SXYZ;
        int rem = key % SXYZ;
        int X = rem / SYZ; rem -= X * SYZ;
        int Y = rem / SZ;
        int Z = rem - Y * SZ;
        ((float4*)oc)[r] = make_float4((float)B, (float)Z, (float)Y, (float)X);
        r++;
    }
}

__global__ void k_wsum(const float* __restrict__ W1) {
    int j = blockIdx.x * 256 + threadIdx.x;
    if (j < 8192) g_wsum[j] = W1[j] + W1[j + 8192];
}

/* feature moments + multi-seg xmax; NO y0 materialization */
__global__ void __launch_bounds__(256) k_prep(const float* __restrict__ pts,
                                              const float* __restrict__ W0) {
    __shared__ float w0s[640];
    __shared__ float sm[65];
    int tid = threadIdx.x;
    for (int j = tid; j < 640; j += 256) w0s[j] = W0[j];
    if (tid < 65) sm[tid] = 0.f;
    __syncthreads();
    float mom[65];
    #pragma unroll
    for (int v = 0; v < 65; v++) mom[v] = 0.f;
    int base = blockIdx.x * 2048;
    for (int i = base + tid; i < base + 2048 && i < NP; i += 256) {
        float f[10];
        int seg, cnt;
        compute_feat(pts, i, f, seg, cnt);
        #pragma unroll
        for (int k = 0; k < 10; k++) mom[k] += f[k];
        {
            int idx = 10;
            #pragma unroll
            for (int k = 0; k < 10; k++)
                #pragma unroll
                for (int l = k; l < 10; l++)
                    mom[idx++] += f[k] * f[l];
        }
        if (cnt > 1) {
            int mi = atomicAdd(&g_nmulti, 1);
            g_mlist[mi] = i;
            unsigned* xm = &g_xmaxu[(size_t)seg * 64];
            #pragma unroll 8
            for (int c = 0; c < 64; c++) {
                float acc = 0.f;
                #pragma unroll
                for (int k = 0; k < 10; k++) acc = fmaf(f[k], w0s[k * 64 + c], acc);
                atomicMax(&xm[c], utrans(acc));
            }
        }
    }
    int lane = tid & 31;
    #pragma unroll
    for (int v = 0; v < 65; v++) {
        float s = mom[v];
        #pragma unroll
        for (int o = 16; o; o >>= 1) s += __shfl_down_sync(0xffffffffu, s, o);
        if (lane == 0) atomicAdd(&sm[v], s);
    }
    __syncthreads();
    if (tid < 65) atomicAdd(&g_mom[tid], (double)sm[tid]);
}

/* BN0 stats by bilinearity of moments */
__global__ void k_bn0(const float* __restrict__ W0,
                      const float* __restrict__ g, const float* __restrict__ b) {
    int c = threadIdx.x;
    if (c >= 64) return;
    double w[10];
    #pragma unroll
    for (int k = 0; k < 10; k++) w[k] = (double)W0[k * 64 + c];
    double mean = 0.0;
    #pragma unroll
    for (int k = 0; k < 10; k++) mean += w[k] * g_mom[k];
    mean /= (double)NP;
    double ey2 = 0.0;
    int idx = 10;
    #pragma unroll
    for (int k = 0; k < 10; k++)
        #pragma unroll
        for (int l = k; l < 10; l++) {
            double t = w[k] * w[l] * g_mom[idx++];
            ey2 += (k == l) ? t : 2.0 * t;
        }
    ey2 /= (double)NP;
    double var = ey2 - mean * mean;
    double s = (double)g[c] / sqrt(var + 0.001);
    g_s0[c] = (float)s;
    g_t0[c] = (float)((double)b[c] - mean * s);
}

/* Pass A: y1 = h0 @ (W1a+W1b), h0 recomputed from pts (no y0) */
__global__ void __launch_bounds__(256, 2) k_gemm1(const float* __restrict__ pts,
                                                  const float* __restrict__ W0) {
    extern __shared__ float sh[];
    float* ws = sh;            /* 64*128 */
    float* xs = sh + 8192;     /* 64*132 */
    __shared__ float w0s[640];
    __shared__ float sS[64], sT[64];
    int tid = threadIdx.x;
    if (tid < 64)  { sS[tid] = g_s0[tid]; sT[tid] = g_t0[tid]; }
    for (int j = tid; j < 640; j += 256) w0s[j] = W0[j];
    {
        const float4* w4 = (const float4*)g_wsum;
        float4* ws4 = (float4*)ws;
        for (int j = tid; j < 2048; j += 256) ws4[j] = w4[j];
    }
    __syncthreads();

    int bs = blockIdx.x * 128;
    {
        int m = tid & 127, half = tid >> 7;
        float f[10];
        int seg, cnt;
        compute_feat(pts, bs + m, f, seg, cnt);
        int cbase = half * 32;
        #pragma unroll 8
        for (int c = cbase; c < cbase + 32; c++) {
            float acc = 0.f;
            #pragma unroll
            for (int k = 0; k < 10; k++) acc = fmaf(f[k], w0s[k * 64 + c], acc);
            xs[c * 132 + m] = fmaxf(fmaf(acc, sS[c], sT[c]), 0.f);
        }
    }
    __syncthreads();

    int tx = tid & 15, ty = tid >> 4;
    unsigned long long acc[8][4];
    #pragma unroll
    for (int i = 0; i < 8; i++)
        #pragma unroll
        for (int p = 0; p < 4; p++) acc[i][p] = 0ull;

    #pragma unroll 2
    for (int k = 0; k < 64; k++) {
        float4 a0 = *(const float4*)&xs[k * 132 + ty * 8];
        float4 a1 = *(const float4*)&xs[k * 132 + ty * 8 + 4];
        unsigned long long am[8];
        am[0] = pk2(a0.x, a0.x); am[1] = pk2(a0.y, a0.y);
        am[2] = pk2(a0.z, a0.z); am[3] = pk2(a0.w, a0.w);
        am[4] = pk2(a1.x, a1.x); am[5] = pk2(a1.y, a1.y);
        am[6] = pk2(a1.z, a1.z); am[7] = pk2(a1.w, a1.w);
        ulonglong2 b0 = *(const ulonglong2*)&ws[k * 128 + tx * 8];
        ulonglong2 b1 = *(const ulonglong2*)&ws[k * 128 + tx * 8 + 4];
        #pragma unroll
        for (int i = 0; i < 8; i++) {
            acc[i][0] = fma2(am[i], b0.x, acc[i][0]);
            acc[i][1] = fma2(am[i], b0.y, acc[i][1]);
            acc[i][2] = fma2(am[i], b1.x, acc[i][2]);
            acc[i][3] = fma2(am[i], b1.y, acc[i][3]);
        }
    }

    float cs[8] = {0,0,0,0,0,0,0,0}, cs2[8] = {0,0,0,0,0,0,0,0};
    #pragma unroll
    for (int i = 0; i < 8; i++) {
        float v[8];
        #pragma unroll
        for (int p = 0; p < 4; p++) upk(acc[i][p], v[2 * p], v[2 * p + 1]);
        int pt = bs + ty * 8 + i;
        float4* dst = (float4*)&g_y1[(size_t)pt * 128 + tx * 8];
        dst[0] = make_float4(v[0], v[1], v[2], v[3]);
        dst[1] = make_float4(v[4], v[5], v[6], v[7]);
        #pragma unroll
        for (int j = 0; j < 8; j++) { cs[j] += v[j]; cs2[j] += v[j] * v[j]; }
    }
    __syncthreads();
    #pragma unroll
    for (int j = 0; j < 8; j++) xs[ty * 128 + tx * 8 + j] = cs[j];
    __syncthreads();
    if (tid < 128) {
        float s = 0.f;
        #pragma unroll
        for (int r = 0; r < 16; r++) s += xs[r * 128 + tid];
        atomicAdd(&g_st[128 + tid], (double)s);
    }
    __syncthreads();
    #pragma unroll
    for (int j = 0; j < 8; j++) xs[ty * 128 + tx * 8 + j] = cs2[j];
    __syncthreads();
    if (tid < 128) {
        float s = 0.f;
        #pragma unroll
        for (int r = 0; r < 16; r++) s += xs[r * 128 + tid];
        atomicAdd(&g_st[256 + tid], (double)s);
    }
}

/* Pass B: multi-seg correction y1 += (hmax - h0) @ W1b, h0 recomputed */
__global__ void k_gemm1b(const float* __restrict__ pts,
                         const float* __restrict__ W0,
                         const float* __restrict__ W1) {
    __shared__ float w0s[640];
    __shared__ float d[64];
    int tid = threadIdx.x;   /* 128 */
    for (int j = tid; j < 640; j += 128) w0s[j] = W0[j];
    __syncthreads();
    double ds1 = 0.0, ds2 = 0.0;
    int nm = g_nmulti;
    for (int it = blockIdx.x; it < nm; it += gridDim.x) {
        int p = g_mlist[it];
        float f[10];
        int seg, cnt;
        compute_feat(pts, p, f, seg, cnt);
        if (tid < 64) {
            float acc = 0.f;
            #pragma unroll
            for (int k = 0; k < 10; k++) acc = fmaf(f[k], w0s[k * 64 + tid], acc);
            float h0 = fmaxf(fmaf(acc, g_s0[tid], g_t0[tid]), 0.f);
            float hm = fmaxf(fmaf(uinv(g_xmaxu[(size_t)seg * 64 + tid]),
                                  g_s0[tid], g_t0[tid]), 0.f);
            d[tid] = hm - h0;
        }
        __syncthreads();
        float acc = 0.f;
        #pragma unroll 8
        for (int k = 0; k < 64; k++)
            acc = fmaf(d[k], W1[(64 + k) * 128 + tid], acc);
        size_t oi = (size_t)p * 128 + tid;
        float old = g_y1[oi];
        float nw = old + acc;
        g_y1[oi] = nw;
        ds1 += (double)acc;
        ds2 += (double)nw * (double)nw - (double)old * (double)old;
        __syncthreads();
    }
    atomicAdd(&g_st[128 + tid], ds1);
    atomicAdd(&g_st[256 + tid], ds2);
}

__global__ void k_bn1(const float* __restrict__ g, const float* __restrict__ b) {
    int c = threadIdx.x;
    if (c >= 128) return;
    double m = g_st[128 + c] / (double)NP;
    double var = g_st[256 + c] / (double)NP - m * m;
    double s = (double)g[c] / sqrt(var + 0.001);
    g_s1[c] = (float)s;
    g_t1[c] = (float)((double)b[c] - m * s);
}

__global__ void k_final(float* __restrict__ out) {
    __shared__ float s1[128], t1[128];
    int tid = threadIdx.x;
    if (tid < 128) { s1[tid] = g_s1[tid]; t1[tid] = g_t1[tid]; }
    __syncthreads();
    int warp = tid >> 5, lane = tid & 31;
    int pbase = blockIdx.x * 64 + warp * 8;
    float4 sv = *(const float4*)&s1[lane * 4];
    float4 tv = *(const float4*)&t1[lane * 4];
    #pragma unroll
    for (int pp = 0; pp < 8; pp++) {
        int p = pbase + pp;
        int seg = g_inv[p];
        int cnt = g_cnt[seg];
        float4 v = *(const float4*)&g_y1[(size_t)p * 128 + lane * 4];
        float4 h;
        h.x = fmaxf(fmaf(v.x, sv.x, tv.x), 0.f);
        h.y = fmaxf(fmaf(v.y, sv.y, tv.y), 0.f);
        h.z = fmaxf(fmaf(v.z, sv.z, tv.z), 0.f);
        h.w = fmaxf(fmaf(v.w, sv.w, tv.w), 0.f);
        if (cnt == 1) {
            *(float4*)&out[(size_t)seg * 128 + lane * 4] = h;
        } else {
            int* ob = (int*)&out[(size_t)seg * 128 + lane * 4];
            atomicMax(&ob[0], __float_as_int(h.x));
            atomicMax(&ob[1], __float_as_int(h.y));
            atomicMax(&ob[2], __float_as_int(h.z));
            atomicMax(&ob[3], __float_as_int(h.w));
        }
    }
}

extern "C" void kernel_launch(void* const* d_in, const int* in_sizes, int n_in,
                              void* d_out, int out_size) {
    const float* pts = (const float*)d_in[0];
    const float* W0  = (const float*)d_in[1];
    const float* g0  = (const float*)d_in[2];
    const float* b0  = (const float*)d_in[3];
    const float* W1  = (const float*)d_in[4];
    const float* g1  = (const float*)d_in[5];
    const float* b1  = (const float*)d_in[6];
    float* out = (float*)d_out;
    float* oc = out + (size_t)NP * 128;
    int emit_coords = ((long long)out_size >= (long long)NP * 132);

    void *p_bits, *p_cnt, *p_sums, *p_st, *p_nm, *p_mom;
    cudaGetSymbolAddress(&p_bits, g_bits);
    cudaGetSymbolAddress(&p_cnt,  g_cnt);
    cudaGetSymbolAddress(&p_sums, g_sums);
    cudaGetSymbolAddress(&p_st,   g_st);
    cudaGetSymbolAddress(&p_nm,   g_nmulti);
    cudaGetSymbolAddress(&p_mom,  g_mom);

    cudaMemsetAsync(p_bits, 0, NWORDS * 4);
    cudaMemsetAsync(p_cnt,  0, NP * 4);
    cudaMemsetAsync(p_sums, 0, NP * 12);
    cudaMemsetAsync(p_st,   0, 384 * 8);
    cudaMemsetAsync(p_nm,   0, 4);
    cudaMemsetAsync(p_mom,  0, 65 * 8);

    k_keys<<<1563, 256>>>(pts);
    k_scan_words<<<SCAN_BLOCKS, 256>>>();
    k_scan_blocks<<<1, 1024>>>();
    k_inv<<<1563, 256>>>(pts);
    k_zero<<<1563, 256>>>(out, oc, emit_coords);
    if (emit_coords) {
        k_coords<<<2750, 256>>>(oc);
    }
    k_wsum<<<32, 256>>>(W1);
    k_prep<<<196, 256>>>(pts, W0);
    k_bn0<<<1, 64>>>(W0, g0, b0);
    cudaFuncSetAttribute(k_gemm1, cudaFuncAttributeMaxDynamicSharedMemorySize, 66560);
    k_gemm1<<<3125, 256, 66560>>>(pts, W0);
    k_gemm1b<<<592, 128>>>(pts, W0, W1);
    k_bn1<<<1, 128>>>(g1, b1);
    k_final<<<6250, 256>>>(out);
}